// round 2
// baseline (speedup 1.0000x reference)
#include <cuda_runtime.h>
#include <cuda_bf16.h>
#include <math.h>

// ---------------------------------------------------------------------------
// TransformerBlock: B=4, N=1024, D=768, H=12, d=64, D_FF=3072
// Round 2: fp32 SIMT GEMMs + fused flash attention (no 192MB scores buffer)
// ---------------------------------------------------------------------------

#define BATCH     4
#define SEQ       1024
#define DIM       768
#define HEADS     12
#define HDIM      64
#define DFF       3072
#define TOKENS    (BATCH * SEQ)      // 4096
#define LN_EPS    1e-6f

// -------------------- scratch (no allocation allowed) ----------------------
__device__ float g_xn [TOKENS * DIM];            // LN1 output
__device__ float g_q  [TOKENS * DIM];            // [B,N,H,d] packed as [4096,768]
__device__ float g_k  [TOKENS * DIM];
__device__ float g_v  [TOKENS * DIM];
__device__ float g_ctx[TOKENS * DIM];
__device__ float g_x1 [TOKENS * DIM];            // x + attn_out
__device__ float g_xn2[TOKENS * DIM];            // LN2 output
__device__ float g_h1 [TOKENS * DFF];            // gelu(xn2@W1+b1)

// ------------------------------ LayerNorm ----------------------------------
__global__ __launch_bounds__(256) void ln_kernel(const float* __restrict__ x,
                                                 const float* __restrict__ g,
                                                 const float* __restrict__ b,
                                                 float* __restrict__ out) {
    int row = blockIdx.x;
    int tid = threadIdx.x;
    const float* xr = x + (size_t)row * DIM;
    __shared__ float buf[DIM];
    __shared__ float red[256];

    float s = 0.f;
    for (int i = tid; i < DIM; i += 256) { float v = xr[i]; buf[i] = v; s += v; }
    red[tid] = s; __syncthreads();
    for (int off = 128; off > 0; off >>= 1) {
        if (tid < off) red[tid] += red[tid + off];
        __syncthreads();
    }
    float mean = red[0] * (1.0f / DIM);
    __syncthreads();

    float vs = 0.f;
    for (int i = tid; i < DIM; i += 256) { float d = buf[i] - mean; vs += d * d; }
    red[tid] = vs; __syncthreads();
    for (int off = 128; off > 0; off >>= 1) {
        if (tid < off) red[tid] += red[tid + off];
        __syncthreads();
    }
    float rstd = rsqrtf(red[0] * (1.0f / DIM) + LN_EPS);

    float* orow = out + (size_t)row * DIM;
    for (int i = tid; i < DIM; i += 256)
        orow[i] = (buf[i] - mean) * rstd * g[i] + b[i];
}

// ------------------------------- GEMM --------------------------------------
// C[M,N] = A[M,K] @ W[K,N] + bias[N]  (+ epilogue)
// EPI: 0 = none, 1 = exact GELU, 2 = add residual R[M,N]
__device__ __forceinline__ float gelu_exact(float v) {
    return 0.5f * v * (1.0f + erff(v * 0.70710678118654752f));
}

template<int EPI>
__global__ __launch_bounds__(256) void gemm_kernel(const float* __restrict__ A,
                                                   const float* __restrict__ W,
                                                   const float* __restrict__ bias,
                                                   const float* __restrict__ R,
                                                   float* __restrict__ C,
                                                   int M, int N, int K) {
    __shared__ float As[16][64];
    __shared__ float Bs[16][64];

    int tid = threadIdx.x;
    int bx = blockIdx.x;   // N tile
    int by = blockIdx.y;   // M tile
    int ty = tid >> 4, tx = tid & 15;

    float acc[4][4];
#pragma unroll
    for (int j = 0; j < 4; j++)
#pragma unroll
        for (int i = 0; i < 4; i++) acc[j][i] = 0.f;

    for (int k0 = 0; k0 < K; k0 += 16) {
#pragma unroll
        for (int i = 0; i < 4; i++) {
            int lin = tid + i * 256;
            int r = lin >> 4, c = lin & 15;
            As[c][r] = A[(size_t)(by * 64 + r) * K + k0 + c];
        }
#pragma unroll
        for (int i = 0; i < 4; i++) {
            int lin = tid + i * 256;
            int c = lin >> 6, n = lin & 63;
            Bs[c][n] = W[(size_t)(k0 + c) * N + bx * 64 + n];
        }
        __syncthreads();
#pragma unroll
        for (int c = 0; c < 16; c++) {
            float4 a = *(const float4*)&As[c][ty * 4];
            float4 bb = *(const float4*)&Bs[c][tx * 4];
            float av[4] = {a.x, a.y, a.z, a.w};
            float bv[4] = {bb.x, bb.y, bb.z, bb.w};
#pragma unroll
            for (int j = 0; j < 4; j++)
#pragma unroll
                for (int i = 0; i < 4; i++) acc[j][i] += av[j] * bv[i];
        }
        __syncthreads();
    }

#pragma unroll
    for (int j = 0; j < 4; j++) {
        int row = by * 64 + ty * 4 + j;
#pragma unroll
        for (int i = 0; i < 4; i++) {
            int col = bx * 64 + tx * 4 + i;
            float v = acc[j][i] + bias[col];
            if (EPI == 1) v = gelu_exact(v);
            if (EPI == 2) v += R[(size_t)row * N + col];
            C[(size_t)row * N + col] = v;
        }
    }
}

// ------------------------- fused flash attention ---------------------------
// One block per (bh, 64-query tile). Online softmax; S never hits GMEM.
// Thread (ty,tx) owns rows ty*4..+3 (queries) and cols tx*4..+3.
__global__ __launch_bounds__(256) void flash_kernel(const float* __restrict__ q,
                                                    const float* __restrict__ k,
                                                    const float* __restrict__ v,
                                                    float* __restrict__ ctx) {
    int bh = blockIdx.z;
    int b = bh / HEADS, h = bh % HEADS;
    int qt = blockIdx.y;
    const float* qb = q + (size_t)b * SEQ * DIM + h * HDIM;
    const float* kb = k + (size_t)b * SEQ * DIM + h * HDIM;
    const float* vb = v + (size_t)b * SEQ * DIM + h * HDIM;
    float* ob = ctx + (size_t)b * SEQ * DIM + h * HDIM;

    __shared__ float Qs[64][64];   // K-major: Qs[c][qrow]
    __shared__ float KV[64][64];   // phase 1: Ks[c][key]; phase 2: Vs[key][n]
    __shared__ float Ps[64][64];   // row-major: Ps[qrow][key]

    int tid = threadIdx.x;
    int ty = tid >> 4, tx = tid & 15;

    // load Q tile, transposed to K-major
#pragma unroll
    for (int kc = 0; kc < 4; kc++)
#pragma unroll
        for (int i = 0; i < 4; i++) {
            int lin = tid + i * 256;
            int r = lin >> 4, c = lin & 15;
            Qs[kc * 16 + c][r] = qb[(size_t)(qt * 64 + r) * DIM + kc * 16 + c];
        }

    float m[4], l[4], O[4][4];
#pragma unroll
    for (int j = 0; j < 4; j++) {
        m[j] = -1e30f; l[j] = 0.f;
#pragma unroll
        for (int i = 0; i < 4; i++) O[j][i] = 0.f;
    }

    for (int t = 0; t < SEQ / 64; t++) {
        __syncthreads();   // KV free (prev PV done); Ps free; Qs visible (t=0)

        // load K tile, transposed to K-major
#pragma unroll
        for (int kc = 0; kc < 4; kc++)
#pragma unroll
            for (int i = 0; i < 4; i++) {
                int lin = tid + i * 256;
                int r = lin >> 4, c = lin & 15;
                KV[kc * 16 + c][r] = kb[(size_t)(t * 64 + r) * DIM + kc * 16 + c];
            }
        __syncthreads();

        // S = Q K^T / 8  (4x4 per thread)
        float acc[4][4];
#pragma unroll
        for (int j = 0; j < 4; j++)
#pragma unroll
            for (int i = 0; i < 4; i++) acc[j][i] = 0.f;
#pragma unroll
        for (int c = 0; c < 64; c++) {
            float4 a = *(const float4*)&Qs[c][ty * 4];
            float4 bb = *(const float4*)&KV[c][tx * 4];
            float av[4] = {a.x, a.y, a.z, a.w};
            float bv[4] = {bb.x, bb.y, bb.z, bb.w};
#pragma unroll
            for (int j = 0; j < 4; j++)
#pragma unroll
                for (int i = 0; i < 4; i++) acc[j][i] += av[j] * bv[i];
        }

        // online softmax update (rows shared by 16 lanes: masks 1..8 stay in-half)
        float p[4][4];
#pragma unroll
        for (int j = 0; j < 4; j++) {
            float tm = fmaxf(fmaxf(acc[j][0], acc[j][1]), fmaxf(acc[j][2], acc[j][3])) * 0.125f;
#pragma unroll
            for (int mask = 8; mask > 0; mask >>= 1)
                tm = fmaxf(tm, __shfl_xor_sync(0xffffffffu, tm, mask));
            float mn = fmaxf(m[j], tm);
            float sc = __expf(m[j] - mn);
            float rs = 0.f;
#pragma unroll
            for (int i = 0; i < 4; i++) {
                p[j][i] = __expf(acc[j][i] * 0.125f - mn);
                rs += p[j][i];
            }
#pragma unroll
            for (int mask = 8; mask > 0; mask >>= 1)
                rs += __shfl_xor_sync(0xffffffffu, rs, mask);
            m[j] = mn;
            l[j] = l[j] * sc + rs;
#pragma unroll
            for (int i = 0; i < 4; i++) O[j][i] *= sc;
        }

        __syncthreads();   // all lanes done reading K from KV

        // store P row-major (float4, conflict-free)
#pragma unroll
        for (int j = 0; j < 4; j++)
            *(float4*)&Ps[ty * 4 + j][tx * 4] = make_float4(p[j][0], p[j][1], p[j][2], p[j][3]);

        // load V tile into KV as Vs[key][n] (coalesced float4)
#pragma unroll
        for (int i = 0; i < 4; i++) {
            int lin4 = tid + i * 256;       // 1024 float4s
            int kk = lin4 >> 4, n4 = lin4 & 15;
            *(float4*)&KV[kk][n4 * 4] =
                *(const float4*)&vb[(size_t)(t * 64 + kk) * DIM + n4 * 4];
        }
        __syncthreads();

        // O += P @ V
#pragma unroll
        for (int kk = 0; kk < 64; kk += 4) {
            float4 pv[4], vv[4];
#pragma unroll
            for (int j = 0; j < 4; j++) pv[j] = *(const float4*)&Ps[ty * 4 + j][kk];
#pragma unroll
            for (int k2 = 0; k2 < 4; k2++) vv[k2] = *(const float4*)&KV[kk + k2][tx * 4];
#pragma unroll
            for (int j = 0; j < 4; j++) {
                float pj[4] = {pv[j].x, pv[j].y, pv[j].z, pv[j].w};
#pragma unroll
                for (int k2 = 0; k2 < 4; k2++) {
                    O[j][0] += pj[k2] * vv[k2].x;
                    O[j][1] += pj[k2] * vv[k2].y;
                    O[j][2] += pj[k2] * vv[k2].z;
                    O[j][3] += pj[k2] * vv[k2].w;
                }
            }
        }
    }

    // normalize and write ctx[b, qrow, h, :]
#pragma unroll
    for (int j = 0; j < 4; j++) {
        float inv = 1.0f / l[j];
        float4 o4 = make_float4(O[j][0] * inv, O[j][1] * inv, O[j][2] * inv, O[j][3] * inv);
        *(float4*)&ob[(size_t)(qt * 64 + ty * 4 + j) * DIM + tx * 4] = o4;
    }
}

// ------------------------------ launcher -----------------------------------
extern "C" void kernel_launch(void* const* d_in, const int* in_sizes, int n_in,
                              void* d_out, int out_size) {
    (void)in_sizes; (void)n_in; (void)out_size;
    const float* x     = (const float*)d_in[0];
    const float* ln1_g = (const float*)d_in[1];
    const float* ln1_b = (const float*)d_in[2];
    const float* Wq    = (const float*)d_in[3];
    const float* bq    = (const float*)d_in[4];
    const float* Wk    = (const float*)d_in[5];
    const float* bk    = (const float*)d_in[6];
    const float* Wv    = (const float*)d_in[7];
    const float* bv    = (const float*)d_in[8];
    const float* Wo    = (const float*)d_in[9];
    const float* bo    = (const float*)d_in[10];
    const float* ln2_g = (const float*)d_in[11];
    const float* ln2_b = (const float*)d_in[12];
    const float* W1    = (const float*)d_in[13];
    const float* b1    = (const float*)d_in[14];
    const float* W2    = (const float*)d_in[15];
    const float* b2    = (const float*)d_in[16];
    float* out = (float*)d_out;

    float *xn, *q, *k, *v, *ctxp, *x1, *xn2, *h1;
    cudaGetSymbolAddress((void**)&xn,   g_xn);
    cudaGetSymbolAddress((void**)&q,    g_q);
    cudaGetSymbolAddress((void**)&k,    g_k);
    cudaGetSymbolAddress((void**)&v,    g_v);
    cudaGetSymbolAddress((void**)&ctxp, g_ctx);
    cudaGetSymbolAddress((void**)&x1,   g_x1);
    cudaGetSymbolAddress((void**)&xn2,  g_xn2);
    cudaGetSymbolAddress((void**)&h1,   g_h1);

    // 1. LN1
    ln_kernel<<<TOKENS, 256>>>(x, ln1_g, ln1_b, xn);

    // 2. Q, K, V projections: [4096,768] @ [768,768]
    gemm_kernel<0><<<dim3(DIM / 64, TOKENS / 64), 256>>>(xn, Wq, bq, nullptr, q, TOKENS, DIM, DIM);
    gemm_kernel<0><<<dim3(DIM / 64, TOKENS / 64), 256>>>(xn, Wk, bk, nullptr, k, TOKENS, DIM, DIM);
    gemm_kernel<0><<<dim3(DIM / 64, TOKENS / 64), 256>>>(xn, Wv, bv, nullptr, v, TOKENS, DIM, DIM);

    // 3. fused attention: softmax(QK^T/8) @ V
    flash_kernel<<<dim3(1, SEQ / 64, BATCH * HEADS), 256>>>(q, k, v, ctxp);

    // 4. attn_out @ Wo + bo + residual(x) -> x1
    gemm_kernel<2><<<dim3(DIM / 64, TOKENS / 64), 256>>>(ctxp, Wo, bo, x, x1, TOKENS, DIM, DIM);

    // 5. LN2
    ln_kernel<<<TOKENS, 256>>>(x1, ln2_g, ln2_b, xn2);

    // 6. h1 = gelu(xn2 @ W1 + b1): [4096,768] @ [768,3072]
    gemm_kernel<1><<<dim3(DFF / 64, TOKENS / 64), 256>>>(xn2, W1, b1, nullptr, h1, TOKENS, DFF, DIM);

    // 7. out = h1 @ W2 + b2 + residual(x1): [4096,3072] @ [3072,768]
    gemm_kernel<2><<<dim3(DIM / 64, TOKENS / 64), 256>>>(h1, W2, b2, x1, out, TOKENS, DIM, DFF);
}

// round 5
// speedup vs baseline: 3.2609x; 3.2609x over previous
#include <cuda_runtime.h>
#include <cuda_fp16.h>
#include <math.h>
#include <stdint.h>

// ---------------------------------------------------------------------------
// TransformerBlock: B=4, N=1024, D=768, H=12, d=64, D_FF=3072
// Round 5 (= round 4 resubmit; infra failure): mma.sync fp16 tensor-core GEMMs
// (tcgen05 unavailable: harness compiles PTX for compute_103, not _103a)
// + fp32 fused flash attention + fp32 LN
// ---------------------------------------------------------------------------

#define BATCH     4
#define SEQ       1024
#define DIM       768
#define HEADS     12
#define HDIM      64
#define DFF       3072
#define TOKENS    (BATCH * SEQ)      // 4096
#define LN_EPS    1e-6f

// -------------------- scratch (no allocation allowed) ----------------------
__device__ float g_xn [TOKENS * DIM];
__device__ float g_q  [TOKENS * DIM];
__device__ float g_k  [TOKENS * DIM];
__device__ float g_v  [TOKENS * DIM];
__device__ float g_ctx[TOKENS * DIM];
__device__ float g_x1 [TOKENS * DIM];
__device__ float g_xn2[TOKENS * DIM];
__device__ float g_h1 [TOKENS * DFF];

// ---------------------------- helpers --------------------------------------
__device__ __forceinline__ uint32_t smem_u32(const void* p) {
    uint32_t a;
    asm("{ .reg .u64 t; cvta.to.shared.u64 t, %1; cvt.u32.u64 %0, t; }" : "=r"(a) : "l"(p));
    return a;
}

__device__ __forceinline__ void ldsm_x4(uint32_t& r0, uint32_t& r1, uint32_t& r2,
                                        uint32_t& r3, uint32_t addr) {
    asm volatile("ldmatrix.sync.aligned.m8n8.x4.shared.b16 {%0,%1,%2,%3}, [%4];"
                 : "=r"(r0), "=r"(r1), "=r"(r2), "=r"(r3) : "r"(addr));
}
__device__ __forceinline__ void ldsm_x4_t(uint32_t& r0, uint32_t& r1, uint32_t& r2,
                                          uint32_t& r3, uint32_t addr) {
    asm volatile("ldmatrix.sync.aligned.m8n8.x4.trans.shared.b16 {%0,%1,%2,%3}, [%4];"
                 : "=r"(r0), "=r"(r1), "=r"(r2), "=r"(r3) : "r"(addr));
}
__device__ __forceinline__ void mma_f16(float* c, const uint32_t* a, const uint32_t* b) {
    asm volatile("mma.sync.aligned.m16n8k16.row.col.f32.f16.f16.f32 "
                 "{%0,%1,%2,%3}, {%4,%5,%6,%7}, {%8,%9}, {%0,%1,%2,%3};"
                 : "+f"(c[0]), "+f"(c[1]), "+f"(c[2]), "+f"(c[3])
                 : "r"(a[0]), "r"(a[1]), "r"(a[2]), "r"(a[3]), "r"(b[0]), "r"(b[1]));
}

__device__ __forceinline__ float gelu_exact(float v) {
    return 0.5f * v * (1.0f + erff(v * 0.70710678118654752f));
}

// --------------------------- fp16 mma GEMM ---------------------------------
// C[M,N] = A[M,K] @ W[K,N] + bias  (EPI: 0=none, 1=gelu, 2=+R)
// CTA: 128x128, BK=32, 8 warps (4 m x 2 n), warp tile 32x64.
#define APAD 40          // 32 + 8 halves
#define BPAD 136         // 128 + 8 halves

template<int EPI>
__global__ __launch_bounds__(256, 1) void gemm_mma(const float* __restrict__ A,
                                                   const float* __restrict__ W,
                                                   const float* __restrict__ bias,
                                                   const float* __restrict__ R,
                                                   float* __restrict__ C,
                                                   int M, int N, int K) {
    __shared__ __half As[2][128][APAD];
    __shared__ __half Bs[2][32][BPAD];

    int tid = threadIdx.x;
    int lane = tid & 31;
    int wid = tid >> 5;
    int wr = wid >> 1;          // 0..3
    int wc = wid & 1;           // 0..1
    int m0 = blockIdx.y * 128;
    int n0 = blockIdx.x * 128;

    float acc[2][8][4];
#pragma unroll
    for (int mi = 0; mi < 2; mi++)
#pragma unroll
        for (int n8 = 0; n8 < 8; n8++)
#pragma unroll
            for (int r = 0; r < 4; r++) acc[mi][n8][r] = 0.f;

    float4 ra[4], rb[4];

    auto glo = [&](int k0) {
#pragma unroll
        for (int it = 0; it < 4; it++) {
            int idx = tid + it * 256;
            int r = idx >> 3, c4 = idx & 7;
            ra[it] = *(const float4*)&A[(size_t)(m0 + r) * K + k0 + c4 * 4];
        }
#pragma unroll
        for (int it = 0; it < 4; it++) {
            int idx = tid + it * 256;
            int r = idx >> 5, c4 = idx & 31;
            rb[it] = *(const float4*)&W[(size_t)(k0 + r) * N + n0 + c4 * 4];
        }
    };
    auto sto = [&](int buf) {
#pragma unroll
        for (int it = 0; it < 4; it++) {
            int idx = tid + it * 256;
            int r = idx >> 3, c4 = idx & 7;
            __half2 h0 = __floats2half2_rn(ra[it].x, ra[it].y);
            __half2 h1 = __floats2half2_rn(ra[it].z, ra[it].w);
            uint2 u;
            u.x = *reinterpret_cast<uint32_t*>(&h0);
            u.y = *reinterpret_cast<uint32_t*>(&h1);
            *(uint2*)&As[buf][r][c4 * 4] = u;
        }
#pragma unroll
        for (int it = 0; it < 4; it++) {
            int idx = tid + it * 256;
            int r = idx >> 5, c4 = idx & 31;
            __half2 h0 = __floats2half2_rn(rb[it].x, rb[it].y);
            __half2 h1 = __floats2half2_rn(rb[it].z, rb[it].w);
            uint2 u;
            u.x = *reinterpret_cast<uint32_t*>(&h0);
            u.y = *reinterpret_cast<uint32_t*>(&h1);
            *(uint2*)&Bs[buf][r][c4 * 4] = u;
        }
    };
    auto compute = [&](int buf) {
        uint32_t a_base = smem_u32(&As[buf][0][0]);
        uint32_t b_base = smem_u32(&Bs[buf][0][0]);
#pragma unroll
        for (int kk = 0; kk < 2; kk++) {
            uint32_t af[2][4];
#pragma unroll
            for (int mi = 0; mi < 2; mi++) {
                int row = wr * 32 + mi * 16 + (lane & 15);
                int col = kk * 16 + (lane >> 4) * 8;
                ldsm_x4(af[mi][0], af[mi][1], af[mi][2], af[mi][3],
                        a_base + (uint32_t)(row * APAD + col) * 2);
            }
            uint32_t bf[4][4];
#pragma unroll
            for (int ni = 0; ni < 4; ni++) {
                int krow = kk * 16 + (lane & 15);
                int col = wc * 64 + ni * 16 + (lane >> 4) * 8;
                ldsm_x4_t(bf[ni][0], bf[ni][1], bf[ni][2], bf[ni][3],
                          b_base + (uint32_t)(krow * BPAD + col) * 2);
            }
#pragma unroll
            for (int mi = 0; mi < 2; mi++)
#pragma unroll
                for (int ni = 0; ni < 4; ni++) {
                    mma_f16(acc[mi][ni * 2],     af[mi], &bf[ni][0]);
                    mma_f16(acc[mi][ni * 2 + 1], af[mi], &bf[ni][2]);
                }
        }
    };

    int nch = K / 32;
    glo(0);
    sto(0);
    __syncthreads();
    for (int i = 0; i < nch; i++) {
        int buf = i & 1;
        if (i + 1 < nch) glo((i + 1) * 32);
        compute(buf);
        if (i + 1 < nch) sto(buf ^ 1);
        __syncthreads();
    }

    // epilogue: c0,c1 -> (row, col..col+1); c2,c3 -> (row+8, ...)
#pragma unroll
    for (int mi = 0; mi < 2; mi++) {
        int row0 = m0 + wr * 32 + mi * 16 + (lane >> 2);
#pragma unroll
        for (int n8 = 0; n8 < 8; n8++) {
            int col = n0 + wc * 64 + n8 * 8 + (lane & 3) * 2;
            float2 bv = *(const float2*)&bias[col];
#pragma unroll
            for (int half = 0; half < 2; half++) {
                int row = row0 + half * 8;
                float vx = acc[mi][n8][half * 2 + 0] + bv.x;
                float vy = acc[mi][n8][half * 2 + 1] + bv.y;
                if (EPI == 1) { vx = gelu_exact(vx); vy = gelu_exact(vy); }
                if (EPI == 2) {
                    float2 rv = *(const float2*)&R[(size_t)row * N + col];
                    vx += rv.x; vy += rv.y;
                }
                *(float2*)&C[(size_t)row * N + col] = make_float2(vx, vy);
            }
        }
    }
}

// ------------------------------ LayerNorm ----------------------------------
__global__ __launch_bounds__(256) void ln_kernel(const float* __restrict__ x,
                                                 const float* __restrict__ g,
                                                 const float* __restrict__ b,
                                                 float* __restrict__ out) {
    int row = blockIdx.x;
    int tid = threadIdx.x;
    const float* xr = x + (size_t)row * DIM;
    __shared__ float buf[DIM];
    __shared__ float red[256];

    float s = 0.f;
    for (int i = tid; i < DIM; i += 256) { float v = xr[i]; buf[i] = v; s += v; }
    red[tid] = s; __syncthreads();
    for (int off = 128; off > 0; off >>= 1) {
        if (tid < off) red[tid] += red[tid + off];
        __syncthreads();
    }
    float mean = red[0] * (1.0f / DIM);
    __syncthreads();

    float vs = 0.f;
    for (int i = tid; i < DIM; i += 256) { float d = buf[i] - mean; vs += d * d; }
    red[tid] = vs; __syncthreads();
    for (int off = 128; off > 0; off >>= 1) {
        if (tid < off) red[tid] += red[tid + off];
        __syncthreads();
    }
    float rstd = rsqrtf(red[0] * (1.0f / DIM) + LN_EPS);

    float* orow = out + (size_t)row * DIM;
    for (int i = tid; i < DIM; i += 256)
        orow[i] = (buf[i] - mean) * rstd * g[i] + b[i];
}

// ------------------------- fused flash attention ---------------------------
__global__ __launch_bounds__(256) void flash_kernel(const float* __restrict__ q,
                                                    const float* __restrict__ k,
                                                    const float* __restrict__ v,
                                                    float* __restrict__ ctx) {
    int bh = blockIdx.z;
    int b = bh / HEADS, h = bh % HEADS;
    int qt = blockIdx.y;
    const float* qb = q + (size_t)b * SEQ * DIM + h * HDIM;
    const float* kb = k + (size_t)b * SEQ * DIM + h * HDIM;
    const float* vb = v + (size_t)b * SEQ * DIM + h * HDIM;
    float* ob = ctx + (size_t)b * SEQ * DIM + h * HDIM;

    __shared__ float Qs[64][64];   // K-major
    __shared__ float KV[64][64];   // K then V
    __shared__ float Ps[64][64];

    int tid = threadIdx.x;
    int ty = tid >> 4, tx = tid & 15;

#pragma unroll
    for (int kc = 0; kc < 4; kc++)
#pragma unroll
        for (int i = 0; i < 4; i++) {
            int lin = tid + i * 256;
            int r = lin >> 4, c = lin & 15;
            Qs[kc * 16 + c][r] = qb[(size_t)(qt * 64 + r) * DIM + kc * 16 + c];
        }

    float m[4], l[4], O[4][4];
#pragma unroll
    for (int j = 0; j < 4; j++) {
        m[j] = -1e30f; l[j] = 0.f;
#pragma unroll
        for (int i = 0; i < 4; i++) O[j][i] = 0.f;
    }

    for (int t = 0; t < SEQ / 64; t++) {
        __syncthreads();
#pragma unroll
        for (int kc = 0; kc < 4; kc++)
#pragma unroll
            for (int i = 0; i < 4; i++) {
                int lin = tid + i * 256;
                int r = lin >> 4, c = lin & 15;
                KV[kc * 16 + c][r] = kb[(size_t)(t * 64 + r) * DIM + kc * 16 + c];
            }
        __syncthreads();

        float acc[4][4];
#pragma unroll
        for (int j = 0; j < 4; j++)
#pragma unroll
            for (int i = 0; i < 4; i++) acc[j][i] = 0.f;
#pragma unroll
        for (int c = 0; c < 64; c++) {
            float4 a = *(const float4*)&Qs[c][ty * 4];
            float4 bb = *(const float4*)&KV[c][tx * 4];
            float av[4] = {a.x, a.y, a.z, a.w};
            float bv[4] = {bb.x, bb.y, bb.z, bb.w};
#pragma unroll
            for (int j = 0; j < 4; j++)
#pragma unroll
                for (int i = 0; i < 4; i++) acc[j][i] += av[j] * bv[i];
        }

        float p[4][4];
#pragma unroll
        for (int j = 0; j < 4; j++) {
            float tm = fmaxf(fmaxf(acc[j][0], acc[j][1]), fmaxf(acc[j][2], acc[j][3])) * 0.125f;
#pragma unroll
            for (int mask = 8; mask > 0; mask >>= 1)
                tm = fmaxf(tm, __shfl_xor_sync(0xffffffffu, tm, mask));
            float mn = fmaxf(m[j], tm);
            float sc = __expf(m[j] - mn);
            float rs = 0.f;
#pragma unroll
            for (int i = 0; i < 4; i++) {
                p[j][i] = __expf(acc[j][i] * 0.125f - mn);
                rs += p[j][i];
            }
#pragma unroll
            for (int mask = 8; mask > 0; mask >>= 1)
                rs += __shfl_xor_sync(0xffffffffu, rs, mask);
            m[j] = mn;
            l[j] = l[j] * sc + rs;
#pragma unroll
            for (int i = 0; i < 4; i++) O[j][i] *= sc;
        }

        __syncthreads();

#pragma unroll
        for (int j = 0; j < 4; j++)
            *(float4*)&Ps[ty * 4 + j][tx * 4] = make_float4(p[j][0], p[j][1], p[j][2], p[j][3]);

#pragma unroll
        for (int i = 0; i < 4; i++) {
            int lin4 = tid + i * 256;
            int kk = lin4 >> 4, n4 = lin4 & 15;
            *(float4*)&KV[kk][n4 * 4] =
                *(const float4*)&vb[(size_t)(t * 64 + kk) * DIM + n4 * 4];
        }
        __syncthreads();

#pragma unroll
        for (int kk = 0; kk < 64; kk += 4) {
            float4 pv[4], vv[4];
#pragma unroll
            for (int j = 0; j < 4; j++) pv[j] = *(const float4*)&Ps[ty * 4 + j][kk];
#pragma unroll
            for (int k2 = 0; k2 < 4; k2++) vv[k2] = *(const float4*)&KV[kk + k2][tx * 4];
#pragma unroll
            for (int j = 0; j < 4; j++) {
                float pj[4] = {pv[j].x, pv[j].y, pv[j].z, pv[j].w};
#pragma unroll
                for (int k2 = 0; k2 < 4; k2++) {
                    O[j][0] += pj[k2] * vv[k2].x;
                    O[j][1] += pj[k2] * vv[k2].y;
                    O[j][2] += pj[k2] * vv[k2].z;
                    O[j][3] += pj[k2] * vv[k2].w;
                }
            }
        }
    }

#pragma unroll
    for (int j = 0; j < 4; j++) {
        float inv = 1.0f / l[j];
        float4 o4 = make_float4(O[j][0] * inv, O[j][1] * inv, O[j][2] * inv, O[j][3] * inv);
        *(float4*)&ob[(size_t)(qt * 64 + ty * 4 + j) * DIM + tx * 4] = o4;
    }
}

// ------------------------------ launcher -----------------------------------
extern "C" void kernel_launch(void* const* d_in, const int* in_sizes, int n_in,
                              void* d_out, int out_size) {
    (void)in_sizes; (void)n_in; (void)out_size;
    const float* x     = (const float*)d_in[0];
    const float* ln1_g = (const float*)d_in[1];
    const float* ln1_b = (const float*)d_in[2];
    const float* Wq    = (const float*)d_in[3];
    const float* bq    = (const float*)d_in[4];
    const float* Wk    = (const float*)d_in[5];
    const float* bk    = (const float*)d_in[6];
    const float* Wv    = (const float*)d_in[7];
    const float* bv    = (const float*)d_in[8];
    const float* Wo    = (const float*)d_in[9];
    const float* bo    = (const float*)d_in[10];
    const float* ln2_g = (const float*)d_in[11];
    const float* ln2_b = (const float*)d_in[12];
    const float* W1    = (const float*)d_in[13];
    const float* b1    = (const float*)d_in[14];
    const float* W2    = (const float*)d_in[15];
    const float* b2    = (const float*)d_in[16];
    float* out = (float*)d_out;

    float *xn, *q, *k, *v, *ctxp, *x1, *xn2, *h1;
    cudaGetSymbolAddress((void**)&xn,   g_xn);
    cudaGetSymbolAddress((void**)&q,    g_q);
    cudaGetSymbolAddress((void**)&k,    g_k);
    cudaGetSymbolAddress((void**)&v,    g_v);
    cudaGetSymbolAddress((void**)&ctxp, g_ctx);
    cudaGetSymbolAddress((void**)&x1,   g_x1);
    cudaGetSymbolAddress((void**)&xn2,  g_xn2);
    cudaGetSymbolAddress((void**)&h1,   g_h1);

    // 1. LN1
    ln_kernel<<<TOKENS, 256>>>(x, ln1_g, ln1_b, xn);

    // 2. QKV projections
    gemm_mma<0><<<dim3(DIM / 128, TOKENS / 128), 256>>>(xn, Wq, bq, nullptr, q, TOKENS, DIM, DIM);
    gemm_mma<0><<<dim3(DIM / 128, TOKENS / 128), 256>>>(xn, Wk, bk, nullptr, k, TOKENS, DIM, DIM);
    gemm_mma<0><<<dim3(DIM / 128, TOKENS / 128), 256>>>(xn, Wv, bv, nullptr, v, TOKENS, DIM, DIM);

    // 3. fused attention
    flash_kernel<<<dim3(1, SEQ / 64, BATCH * HEADS), 256>>>(q, k, v, ctxp);

    // 4. Wo + residual
    gemm_mma<2><<<dim3(DIM / 128, TOKENS / 128), 256>>>(ctxp, Wo, bo, x, x1, TOKENS, DIM, DIM);

    // 5. LN2
    ln_kernel<<<TOKENS, 256>>>(x1, ln2_g, ln2_b, xn2);

    // 6. W1 + GELU
    gemm_mma<1><<<dim3(DFF / 128, TOKENS / 128), 256>>>(xn2, W1, b1, nullptr, h1, TOKENS, DFF, DIM);

    // 7. W2 + residual -> out
    gemm_mma<2><<<dim3(DIM / 128, TOKENS / 128), 256>>>(h1, W2, b2, x1, out, TOKENS, DIM, DFF);
}

// round 6
// speedup vs baseline: 5.8245x; 1.7862x over previous
#include <cuda_runtime.h>
#include <cuda_fp16.h>
#include <math.h>
#include <stdint.h>

// ---------------------------------------------------------------------------
// TransformerBlock: B=4, N=1024, D=768, H=12, d=64, D_FF=3072
// Round 6: fp16 mma.sync everywhere it counts:
//   - fused QKV (one launch, grid.z selects W), fp16 outputs
//   - flash attention on tensor cores (FA-2 register repack, P never in smem)
//   - dense GEMMs (Wo, W1+GELU, W2) as in round 5 (proven)
// ---------------------------------------------------------------------------

#define BATCH     4
#define SEQ       1024
#define DIM       768
#define HEADS     12
#define HDIM      64
#define DFF       3072
#define TOKENS    (BATCH * SEQ)      // 4096
#define LN_EPS    1e-6f

// -------------------- scratch (no allocation allowed) ----------------------
__device__ float  g_xn [TOKENS * DIM];
__device__ __half g_qh [TOKENS * DIM];
__device__ __half g_kh [TOKENS * DIM];
__device__ __half g_vh [TOKENS * DIM];
__device__ float  g_ctx[TOKENS * DIM];
__device__ float  g_x1 [TOKENS * DIM];
__device__ float  g_xn2[TOKENS * DIM];
__device__ float  g_h1 [TOKENS * DFF];

// ---------------------------- helpers --------------------------------------
__device__ __forceinline__ uint32_t smem_u32(const void* p) {
    uint32_t a;
    asm("{ .reg .u64 t; cvta.to.shared.u64 t, %1; cvt.u32.u64 %0, t; }" : "=r"(a) : "l"(p));
    return a;
}
__device__ __forceinline__ void ldsm_x4(uint32_t& r0, uint32_t& r1, uint32_t& r2,
                                        uint32_t& r3, uint32_t addr) {
    asm volatile("ldmatrix.sync.aligned.m8n8.x4.shared.b16 {%0,%1,%2,%3}, [%4];"
                 : "=r"(r0), "=r"(r1), "=r"(r2), "=r"(r3) : "r"(addr));
}
__device__ __forceinline__ void ldsm_x4_t(uint32_t& r0, uint32_t& r1, uint32_t& r2,
                                          uint32_t& r3, uint32_t addr) {
    asm volatile("ldmatrix.sync.aligned.m8n8.x4.trans.shared.b16 {%0,%1,%2,%3}, [%4];"
                 : "=r"(r0), "=r"(r1), "=r"(r2), "=r"(r3) : "r"(addr));
}
__device__ __forceinline__ void mma_f16(float* c, const uint32_t* a, const uint32_t* b) {
    asm volatile("mma.sync.aligned.m16n8k16.row.col.f32.f16.f16.f32 "
                 "{%0,%1,%2,%3}, {%4,%5,%6,%7}, {%8,%9}, {%0,%1,%2,%3};"
                 : "+f"(c[0]), "+f"(c[1]), "+f"(c[2]), "+f"(c[3])
                 : "r"(a[0]), "r"(a[1]), "r"(a[2]), "r"(a[3]), "r"(b[0]), "r"(b[1]));
}
__device__ __forceinline__ float gelu_exact(float v) {
    return 0.5f * v * (1.0f + erff(v * 0.70710678118654752f));
}
__device__ __forceinline__ uint32_t pack_h2(float a, float b) {
    __half2 h = __floats2half2_rn(a, b);
    return *reinterpret_cast<uint32_t*>(&h);
}

// --------------------------- fp16 mma GEMM ---------------------------------
#define APAD 40
#define BPAD 136

template<int EPI>
__global__ __launch_bounds__(256, 1) void gemm_mma(const float* __restrict__ A,
                                                   const float* __restrict__ W,
                                                   const float* __restrict__ bias,
                                                   const float* __restrict__ R,
                                                   float* __restrict__ C,
                                                   int M, int N, int K) {
    __shared__ __half As[2][128][APAD];
    __shared__ __half Bs[2][32][BPAD];

    int tid = threadIdx.x;
    int lane = tid & 31;
    int wid = tid >> 5;
    int wr = wid >> 1, wc = wid & 1;
    int m0 = blockIdx.y * 128, n0 = blockIdx.x * 128;

    float acc[2][8][4];
#pragma unroll
    for (int mi = 0; mi < 2; mi++)
#pragma unroll
        for (int n8 = 0; n8 < 8; n8++)
#pragma unroll
            for (int r = 0; r < 4; r++) acc[mi][n8][r] = 0.f;

    float4 ra[4], rb[4];
    auto glo = [&](int k0) {
#pragma unroll
        for (int it = 0; it < 4; it++) {
            int idx = tid + it * 256;
            int r = idx >> 3, c4 = idx & 7;
            ra[it] = *(const float4*)&A[(size_t)(m0 + r) * K + k0 + c4 * 4];
        }
#pragma unroll
        for (int it = 0; it < 4; it++) {
            int idx = tid + it * 256;
            int r = idx >> 5, c4 = idx & 31;
            rb[it] = *(const float4*)&W[(size_t)(k0 + r) * N + n0 + c4 * 4];
        }
    };
    auto sto = [&](int buf) {
#pragma unroll
        for (int it = 0; it < 4; it++) {
            int idx = tid + it * 256;
            int r = idx >> 3, c4 = idx & 7;
            uint2 u = {pack_h2(ra[it].x, ra[it].y), pack_h2(ra[it].z, ra[it].w)};
            *(uint2*)&As[buf][r][c4 * 4] = u;
        }
#pragma unroll
        for (int it = 0; it < 4; it++) {
            int idx = tid + it * 256;
            int r = idx >> 5, c4 = idx & 31;
            uint2 u = {pack_h2(rb[it].x, rb[it].y), pack_h2(rb[it].z, rb[it].w)};
            *(uint2*)&Bs[buf][r][c4 * 4] = u;
        }
    };
    auto compute = [&](int buf) {
        uint32_t a_base = smem_u32(&As[buf][0][0]);
        uint32_t b_base = smem_u32(&Bs[buf][0][0]);
#pragma unroll
        for (int kk = 0; kk < 2; kk++) {
            uint32_t af[2][4];
#pragma unroll
            for (int mi = 0; mi < 2; mi++) {
                int row = wr * 32 + mi * 16 + (lane & 15);
                int col = kk * 16 + (lane >> 4) * 8;
                ldsm_x4(af[mi][0], af[mi][1], af[mi][2], af[mi][3],
                        a_base + (uint32_t)(row * APAD + col) * 2);
            }
            uint32_t bf[4][4];
#pragma unroll
            for (int ni = 0; ni < 4; ni++) {
                int krow = kk * 16 + (lane & 15);
                int col = wc * 64 + ni * 16 + (lane >> 4) * 8;
                ldsm_x4_t(bf[ni][0], bf[ni][1], bf[ni][2], bf[ni][3],
                          b_base + (uint32_t)(krow * BPAD + col) * 2);
            }
#pragma unroll
            for (int mi = 0; mi < 2; mi++)
#pragma unroll
                for (int ni = 0; ni < 4; ni++) {
                    mma_f16(acc[mi][ni * 2],     af[mi], &bf[ni][0]);
                    mma_f16(acc[mi][ni * 2 + 1], af[mi], &bf[ni][2]);
                }
        }
    };

    int nch = K / 32;
    glo(0); sto(0); __syncthreads();
    for (int i = 0; i < nch; i++) {
        int buf = i & 1;
        if (i + 1 < nch) glo((i + 1) * 32);
        compute(buf);
        if (i + 1 < nch) sto(buf ^ 1);
        __syncthreads();
    }

#pragma unroll
    for (int mi = 0; mi < 2; mi++) {
        int row0 = m0 + wr * 32 + mi * 16 + (lane >> 2);
#pragma unroll
        for (int n8 = 0; n8 < 8; n8++) {
            int col = n0 + wc * 64 + n8 * 8 + (lane & 3) * 2;
            float2 bv = *(const float2*)&bias[col];
#pragma unroll
            for (int half = 0; half < 2; half++) {
                int row = row0 + half * 8;
                float vx = acc[mi][n8][half * 2 + 0] + bv.x;
                float vy = acc[mi][n8][half * 2 + 1] + bv.y;
                if (EPI == 1) { vx = gelu_exact(vx); vy = gelu_exact(vy); }
                if (EPI == 2) {
                    float2 rv = *(const float2*)&R[(size_t)row * N + col];
                    vx += rv.x; vy += rv.y;
                }
                *(float2*)&C[(size_t)row * N + col] = make_float2(vx, vy);
            }
        }
    }
}

// ----------------------- fused QKV GEMM (fp16 out) -------------------------
// grid (6, 32, 3): z selects (W, bias, out). Same body as gemm_mma, EPI=0.
__global__ __launch_bounds__(256, 1) void qkv_mma(const float* __restrict__ A,
                                                  const float* __restrict__ W0,
                                                  const float* __restrict__ W1,
                                                  const float* __restrict__ W2,
                                                  const float* __restrict__ b0,
                                                  const float* __restrict__ b1,
                                                  const float* __restrict__ b2,
                                                  __half* __restrict__ o0,
                                                  __half* __restrict__ o1,
                                                  __half* __restrict__ o2) {
    const int M = TOKENS, N = DIM, K = DIM;
    const float* W = (blockIdx.z == 0) ? W0 : (blockIdx.z == 1) ? W1 : W2;
    const float* bias = (blockIdx.z == 0) ? b0 : (blockIdx.z == 1) ? b1 : b2;
    __half* O = (blockIdx.z == 0) ? o0 : (blockIdx.z == 1) ? o1 : o2;

    __shared__ __half As[2][128][APAD];
    __shared__ __half Bs[2][32][BPAD];

    int tid = threadIdx.x;
    int lane = tid & 31;
    int wid = tid >> 5;
    int wr = wid >> 1, wc = wid & 1;
    int m0 = blockIdx.y * 128, n0 = blockIdx.x * 128;

    float acc[2][8][4];
#pragma unroll
    for (int mi = 0; mi < 2; mi++)
#pragma unroll
        for (int n8 = 0; n8 < 8; n8++)
#pragma unroll
            for (int r = 0; r < 4; r++) acc[mi][n8][r] = 0.f;

    float4 ra[4], rb[4];
    auto glo = [&](int k0) {
#pragma unroll
        for (int it = 0; it < 4; it++) {
            int idx = tid + it * 256;
            int r = idx >> 3, c4 = idx & 7;
            ra[it] = *(const float4*)&A[(size_t)(m0 + r) * K + k0 + c4 * 4];
        }
#pragma unroll
        for (int it = 0; it < 4; it++) {
            int idx = tid + it * 256;
            int r = idx >> 5, c4 = idx & 31;
            rb[it] = *(const float4*)&W[(size_t)(k0 + r) * N + n0 + c4 * 4];
        }
    };
    auto sto = [&](int buf) {
#pragma unroll
        for (int it = 0; it < 4; it++) {
            int idx = tid + it * 256;
            int r = idx >> 3, c4 = idx & 7;
            uint2 u = {pack_h2(ra[it].x, ra[it].y), pack_h2(ra[it].z, ra[it].w)};
            *(uint2*)&As[buf][r][c4 * 4] = u;
        }
#pragma unroll
        for (int it = 0; it < 4; it++) {
            int idx = tid + it * 256;
            int r = idx >> 5, c4 = idx & 31;
            uint2 u = {pack_h2(rb[it].x, rb[it].y), pack_h2(rb[it].z, rb[it].w)};
            *(uint2*)&Bs[buf][r][c4 * 4] = u;
        }
    };
    auto compute = [&](int buf) {
        uint32_t a_base = smem_u32(&As[buf][0][0]);
        uint32_t b_base = smem_u32(&Bs[buf][0][0]);
#pragma unroll
        for (int kk = 0; kk < 2; kk++) {
            uint32_t af[2][4];
#pragma unroll
            for (int mi = 0; mi < 2; mi++) {
                int row = wr * 32 + mi * 16 + (lane & 15);
                int col = kk * 16 + (lane >> 4) * 8;
                ldsm_x4(af[mi][0], af[mi][1], af[mi][2], af[mi][3],
                        a_base + (uint32_t)(row * APAD + col) * 2);
            }
            uint32_t bf[4][4];
#pragma unroll
            for (int ni = 0; ni < 4; ni++) {
                int krow = kk * 16 + (lane & 15);
                int col = wc * 64 + ni * 16 + (lane >> 4) * 8;
                ldsm_x4_t(bf[ni][0], bf[ni][1], bf[ni][2], bf[ni][3],
                          b_base + (uint32_t)(krow * BPAD + col) * 2);
            }
#pragma unroll
            for (int mi = 0; mi < 2; mi++)
#pragma unroll
                for (int ni = 0; ni < 4; ni++) {
                    mma_f16(acc[mi][ni * 2],     af[mi], &bf[ni][0]);
                    mma_f16(acc[mi][ni * 2 + 1], af[mi], &bf[ni][2]);
                }
        }
    };

    int nch = K / 32;
    glo(0); sto(0); __syncthreads();
    for (int i = 0; i < nch; i++) {
        int buf = i & 1;
        if (i + 1 < nch) glo((i + 1) * 32);
        compute(buf);
        if (i + 1 < nch) sto(buf ^ 1);
        __syncthreads();
    }

#pragma unroll
    for (int mi = 0; mi < 2; mi++) {
        int row0 = m0 + wr * 32 + mi * 16 + (lane >> 2);
#pragma unroll
        for (int n8 = 0; n8 < 8; n8++) {
            int col = n0 + wc * 64 + n8 * 8 + (lane & 3) * 2;
            float2 bv = *(const float2*)&bias[col];
#pragma unroll
            for (int half = 0; half < 2; half++) {
                int row = row0 + half * 8;
                float vx = acc[mi][n8][half * 2 + 0] + bv.x;
                float vy = acc[mi][n8][half * 2 + 1] + bv.y;
                *(uint32_t*)&O[(size_t)row * N + col] = pack_h2(vx, vy);
            }
        }
    }
}

// ------------------------------ LayerNorm ----------------------------------
__global__ __launch_bounds__(256) void ln_kernel(const float* __restrict__ x,
                                                 const float* __restrict__ g,
                                                 const float* __restrict__ b,
                                                 float* __restrict__ out) {
    int row = blockIdx.x;
    int tid = threadIdx.x;
    const float* xr = x + (size_t)row * DIM;
    __shared__ float buf[DIM];
    __shared__ float red[256];

    float s = 0.f;
    for (int i = tid; i < DIM; i += 256) { float v = xr[i]; buf[i] = v; s += v; }
    red[tid] = s; __syncthreads();
    for (int off = 128; off > 0; off >>= 1) {
        if (tid < off) red[tid] += red[tid + off];
        __syncthreads();
    }
    float mean = red[0] * (1.0f / DIM);
    __syncthreads();

    float vs = 0.f;
    for (int i = tid; i < DIM; i += 256) { float d = buf[i] - mean; vs += d * d; }
    red[tid] = vs; __syncthreads();
    for (int off = 128; off > 0; off >>= 1) {
        if (tid < off) red[tid] += red[tid + off];
        __syncthreads();
    }
    float rstd = rsqrtf(red[0] * (1.0f / DIM) + LN_EPS);

    float* orow = out + (size_t)row * DIM;
    for (int i = tid; i < DIM; i += 256)
        orow[i] = (buf[i] - mean) * rstd * g[i] + b[i];
}

// --------------------- flash attention on tensor cores ---------------------
// 128 threads = 4 warps; warp w owns query rows [qt*64 + 16w, +16).
// Per lane: rows r0 = lane>>2, r1 = r0+8 of the warp tile.
#define FPAD 72

__global__ __launch_bounds__(128) void flash_mma(const __half* __restrict__ q,
                                                 const __half* __restrict__ k,
                                                 const __half* __restrict__ v,
                                                 float* __restrict__ ctx) {
    int bh = blockIdx.z;
    int b = bh / HEADS, h = bh % HEADS;
    int qt = blockIdx.y;
    const __half* qb = q + (size_t)b * SEQ * DIM + h * HDIM;
    const __half* kb = k + (size_t)b * SEQ * DIM + h * HDIM;
    const __half* vb = v + (size_t)b * SEQ * DIM + h * HDIM;
    float* ob = ctx + (size_t)b * SEQ * DIM + h * HDIM;

    __shared__ __half Qs[64][FPAD];
    __shared__ __half Ks[64][FPAD];
    __shared__ __half Vs[64][FPAD];

    int tid = threadIdx.x;
    int lane = tid & 31;
    int w = tid >> 5;

    // load Q tile (64 x 64 halves)
#pragma unroll
    for (int it = 0; it < 4; it++) {
        int idx = tid + it * 128;        // 512 uint4 slots
        int r = idx >> 3, c8 = idx & 7;
        *(uint4*)&Qs[r][c8 * 8] = *(const uint4*)&qb[(size_t)(qt * 64 + r) * DIM + c8 * 8];
    }
    __syncthreads();

    // hoist Q fragments (reused across all 16 key tiles)
    uint32_t qf[4][4];
#pragma unroll
    for (int kk = 0; kk < 4; kk++) {
        int row = w * 16 + (lane & 15);
        int col = kk * 16 + (lane >> 4) * 8;
        ldsm_x4(qf[kk][0], qf[kk][1], qf[kk][2], qf[kk][3],
                smem_u32(&Qs[row][col]));
    }

    float m0 = -1e30f, m1 = -1e30f, l0 = 0.f, l1 = 0.f;
    float o[8][4];
#pragma unroll
    for (int j = 0; j < 8; j++)
#pragma unroll
        for (int r = 0; r < 4; r++) o[j][r] = 0.f;

    for (int t = 0; t < SEQ / 64; t++) {
        // load K and V tiles
#pragma unroll
        for (int it = 0; it < 4; it++) {
            int idx = tid + it * 128;
            int r = idx >> 3, c8 = idx & 7;
            *(uint4*)&Ks[r][c8 * 8] = *(const uint4*)&kb[(size_t)(t * 64 + r) * DIM + c8 * 8];
            *(uint4*)&Vs[r][c8 * 8] = *(const uint4*)&vb[(size_t)(t * 64 + r) * DIM + c8 * 8];
        }
        __syncthreads();

        // S = Q K^T: frags s[j], j = 2*ntile + (keys high/low 8)
        float s[8][4];
#pragma unroll
        for (int j = 0; j < 8; j++)
#pragma unroll
            for (int r = 0; r < 4; r++) s[j][r] = 0.f;
#pragma unroll
        for (int kk = 0; kk < 4; kk++) {
#pragma unroll
            for (int nt = 0; nt < 4; nt++) {
                // non-trans ldmatrix on K[key][d]: B frag for n=key, k=d
                int krow = nt * 16 + (lane & 7) + ((lane >> 4) << 3);
                int kcol = kk * 16 + ((lane >> 3) & 1) * 8;
                uint32_t kf[4];
                ldsm_x4(kf[0], kf[1], kf[2], kf[3], smem_u32(&Ks[krow][kcol]));
                mma_f16(s[nt * 2],     qf[kk], &kf[0]);
                mma_f16(s[nt * 2 + 1], qf[kk], &kf[2]);
            }
        }

        // online softmax on fragments (rows r0, r1 per lane)
        float tm0 = -1e30f, tm1 = -1e30f;
#pragma unroll
        for (int j = 0; j < 8; j++) {
#pragma unroll
            for (int r = 0; r < 4; r++) s[j][r] *= 0.125f;
            tm0 = fmaxf(tm0, fmaxf(s[j][0], s[j][1]));
            tm1 = fmaxf(tm1, fmaxf(s[j][2], s[j][3]));
        }
#pragma unroll
        for (int mask = 1; mask <= 2; mask <<= 1) {
            tm0 = fmaxf(tm0, __shfl_xor_sync(0xffffffffu, tm0, mask));
            tm1 = fmaxf(tm1, __shfl_xor_sync(0xffffffffu, tm1, mask));
        }
        float mn0 = fmaxf(m0, tm0), mn1 = fmaxf(m1, tm1);
        float sc0 = __expf(m0 - mn0), sc1 = __expf(m1 - mn1);
        m0 = mn0; m1 = mn1;

        uint32_t ph0[8], ph1[8];     // packed P halves, rows r0 / r1
        float rs0 = 0.f, rs1 = 0.f;
#pragma unroll
        for (int j = 0; j < 8; j++) {
            float p0 = __expf(s[j][0] - mn0), p1 = __expf(s[j][1] - mn0);
            float p2 = __expf(s[j][2] - mn1), p3 = __expf(s[j][3] - mn1);
            rs0 += p0 + p1; rs1 += p2 + p3;
            ph0[j] = pack_h2(p0, p1);
            ph1[j] = pack_h2(p2, p3);
        }
#pragma unroll
        for (int mask = 1; mask <= 2; mask <<= 1) {
            rs0 += __shfl_xor_sync(0xffffffffu, rs0, mask);
            rs1 += __shfl_xor_sync(0xffffffffu, rs1, mask);
        }
        l0 = l0 * sc0 + rs0;
        l1 = l1 * sc1 + rs1;
#pragma unroll
        for (int j = 0; j < 8; j++) {
            o[j][0] *= sc0; o[j][1] *= sc0;
            o[j][2] *= sc1; o[j][3] *= sc1;
        }

        // O += P @ V : A frags repacked from P, B frags = ldmatrix.trans on V
#pragma unroll
        for (int kk = 0; kk < 4; kk++) {
            uint32_t a[4] = {ph0[2 * kk], ph1[2 * kk], ph0[2 * kk + 1], ph1[2 * kk + 1]};
#pragma unroll
            for (int nt = 0; nt < 4; nt++) {
                int vrow = kk * 16 + (lane & 15);
                int vcol = nt * 16 + (lane >> 4) * 8;
                uint32_t vf[4];
                ldsm_x4_t(vf[0], vf[1], vf[2], vf[3], smem_u32(&Vs[vrow][vcol]));
                mma_f16(o[nt * 2],     a, &vf[0]);
                mma_f16(o[nt * 2 + 1], a, &vf[2]);
            }
        }
        __syncthreads();
    }

    // normalize and write ctx (fp32)
    float inv0 = 1.0f / l0, inv1 = 1.0f / l1;
    int row0 = qt * 64 + w * 16 + (lane >> 2);
    int row1 = row0 + 8;
#pragma unroll
    for (int j = 0; j < 8; j++) {
        int col = (j >> 1) * 16 + (j & 1) * 8 + (lane & 3) * 2;
        *(float2*)&ob[(size_t)row0 * DIM + col] = make_float2(o[j][0] * inv0, o[j][1] * inv0);
        *(float2*)&ob[(size_t)row1 * DIM + col] = make_float2(o[j][2] * inv1, o[j][3] * inv1);
    }
}

// ------------------------------ launcher -----------------------------------
extern "C" void kernel_launch(void* const* d_in, const int* in_sizes, int n_in,
                              void* d_out, int out_size) {
    (void)in_sizes; (void)n_in; (void)out_size;
    const float* x     = (const float*)d_in[0];
    const float* ln1_g = (const float*)d_in[1];
    const float* ln1_b = (const float*)d_in[2];
    const float* Wq    = (const float*)d_in[3];
    const float* bq    = (const float*)d_in[4];
    const float* Wk    = (const float*)d_in[5];
    const float* bk    = (const float*)d_in[6];
    const float* Wv    = (const float*)d_in[7];
    const float* bv    = (const float*)d_in[8];
    const float* Wo    = (const float*)d_in[9];
    const float* bo    = (const float*)d_in[10];
    const float* ln2_g = (const float*)d_in[11];
    const float* ln2_b = (const float*)d_in[12];
    const float* W1    = (const float*)d_in[13];
    const float* b1    = (const float*)d_in[14];
    const float* W2    = (const float*)d_in[15];
    const float* b2    = (const float*)d_in[16];
    float* out = (float*)d_out;

    float *xn, *ctxp, *x1, *xn2, *h1;
    __half *qh, *kh, *vh;
    cudaGetSymbolAddress((void**)&xn,   g_xn);
    cudaGetSymbolAddress((void**)&qh,   g_qh);
    cudaGetSymbolAddress((void**)&kh,   g_kh);
    cudaGetSymbolAddress((void**)&vh,   g_vh);
    cudaGetSymbolAddress((void**)&ctxp, g_ctx);
    cudaGetSymbolAddress((void**)&x1,   g_x1);
    cudaGetSymbolAddress((void**)&xn2,  g_xn2);
    cudaGetSymbolAddress((void**)&h1,   g_h1);

    // 1. LN1
    ln_kernel<<<TOKENS, 256>>>(x, ln1_g, ln1_b, xn);

    // 2. fused QKV (one launch, fp16 outputs)
    qkv_mma<<<dim3(DIM / 128, TOKENS / 128, 3), 256>>>(xn, Wq, Wk, Wv, bq, bk, bv, qh, kh, vh);

    // 3. flash attention on tensor cores
    flash_mma<<<dim3(1, SEQ / 64, BATCH * HEADS), 128>>>(qh, kh, vh, ctxp);

    // 4. Wo + residual
    gemm_mma<2><<<dim3(DIM / 128, TOKENS / 128), 256>>>(ctxp, Wo, bo, x, x1, TOKENS, DIM, DIM);

    // 5. LN2
    ln_kernel<<<TOKENS, 256>>>(x1, ln2_g, ln2_b, xn2);

    // 6. W1 + GELU
    gemm_mma<1><<<dim3(DFF / 128, TOKENS / 128), 256>>>(xn2, W1, b1, nullptr, h1, TOKENS, DFF, DIM);

    // 7. W2 + residual -> out
    gemm_mma<2><<<dim3(DIM / 128, TOKENS / 128), 256>>>(h1, W2, b2, x1, out, TOKENS, DIM, DFF);
}

// round 10
// speedup vs baseline: 8.1172x; 1.3936x over previous
#include <cuda_runtime.h>
#include <cuda_fp16.h>
#include <math.h>
#include <stdint.h>

// ---------------------------------------------------------------------------
// TransformerBlock: B=4, N=1024, D=768, H=12, d=64, D_FF=3072
// Round 10 (= round 8 resubmit; two GPU acquisition timeouts): round 7 +
// cp.async wait fix (empty commit_group keeps the group count uniform so
// wait_group<1> always covers chunk i; the last chunk was previously read
// unsynchronized -> rel_err 9.7e-3).
// ---------------------------------------------------------------------------

#define BATCH     4
#define SEQ       1024
#define DIM       768
#define HEADS     12
#define HDIM      64
#define DFF       3072
#define TOKENS    (BATCH * SEQ)      // 4096
#define LN_EPS    1e-6f

// -------------------- scratch (no allocation allowed) ----------------------
__device__ __half g_xnh [TOKENS * DIM];
__device__ __half g_qh  [TOKENS * DIM];
__device__ __half g_kh  [TOKENS * DIM];
__device__ __half g_vh  [TOKENS * DIM];
__device__ __half g_ctxh[TOKENS * DIM];
__device__ float  g_x1  [TOKENS * DIM];
__device__ __half g_xn2h[TOKENS * DIM];
__device__ __half g_h1h [TOKENS * DFF];
// fp16 weight copies (converted once per launch)
__device__ __half g_Wqh[DIM * DIM];
__device__ __half g_Wkh[DIM * DIM];
__device__ __half g_Wvh[DIM * DIM];
__device__ __half g_Woh[DIM * DIM];
__device__ __half g_W1h[DIM * DFF];
__device__ __half g_W2h[DFF * DIM];

// ---------------------------- helpers --------------------------------------
__device__ __forceinline__ uint32_t smem_u32(const void* p) {
    uint32_t a;
    asm("{ .reg .u64 t; cvta.to.shared.u64 t, %1; cvt.u32.u64 %0, t; }" : "=r"(a) : "l"(p));
    return a;
}
__device__ __forceinline__ void ldsm_x4(uint32_t& r0, uint32_t& r1, uint32_t& r2,
                                        uint32_t& r3, uint32_t addr) {
    asm volatile("ldmatrix.sync.aligned.m8n8.x4.shared.b16 {%0,%1,%2,%3}, [%4];"
                 : "=r"(r0), "=r"(r1), "=r"(r2), "=r"(r3) : "r"(addr));
}
__device__ __forceinline__ void ldsm_x4_t(uint32_t& r0, uint32_t& r1, uint32_t& r2,
                                          uint32_t& r3, uint32_t addr) {
    asm volatile("ldmatrix.sync.aligned.m8n8.x4.trans.shared.b16 {%0,%1,%2,%3}, [%4];"
                 : "=r"(r0), "=r"(r1), "=r"(r2), "=r"(r3) : "r"(addr));
}
__device__ __forceinline__ void mma_f16(float* c, const uint32_t* a, const uint32_t* b) {
    asm volatile("mma.sync.aligned.m16n8k16.row.col.f32.f16.f16.f32 "
                 "{%0,%1,%2,%3}, {%4,%5,%6,%7}, {%8,%9}, {%0,%1,%2,%3};"
                 : "+f"(c[0]), "+f"(c[1]), "+f"(c[2]), "+f"(c[3])
                 : "r"(a[0]), "r"(a[1]), "r"(a[2]), "r"(a[3]), "r"(b[0]), "r"(b[1]));
}
__device__ __forceinline__ void cp16(uint32_t dst, const void* src) {
    asm volatile("cp.async.cg.shared.global [%0], [%1], 16;" :: "r"(dst), "l"(src));
}
__device__ __forceinline__ void cp_commit() {
    asm volatile("cp.async.commit_group;");
}
template<int N>
__device__ __forceinline__ void cp_wait() {
    asm volatile("cp.async.wait_group %0;" :: "n"(N));
}
__device__ __forceinline__ float gelu_exact(float v) {
    return 0.5f * v * (1.0f + erff(v * 0.70710678118654752f));
}
__device__ __forceinline__ uint32_t pack_h2(float a, float b) {
    __half2 h = __floats2half2_rn(a, b);
    return *reinterpret_cast<uint32_t*>(&h);
}

// --------------------- fp16 cp.async pipelined GEMM ------------------------
// C[M,N] = A[M,K] @ W[K,N] + bias  (EPI: 0=none, 1=gelu, 2=+R(fp32))
// CTA 128x128, BK=32, 3-stage cp.async, 8 warps (4m x 2n), warp tile 32x64.
#define ASTRIDE 40                      // halves per A smem row
#define BSTRIDE 136                     // halves per B smem row
#define A_STG   (128 * ASTRIDE * 2)     // 10240 B
#define B_STG   (32 * BSTRIDE * 2)      // 8704 B
#define A_SM_OFF 0
#define B_SM_OFF (3 * A_STG)
#define GEMM_SMEM (3 * (A_STG + B_STG)) // 56832 B

template<int EPI, typename OutT>
__device__ __forceinline__ void gemm_body(const __half* __restrict__ A,
                                          const __half* __restrict__ W,
                                          const float* __restrict__ bias,
                                          const float* __restrict__ R,
                                          OutT* __restrict__ C,
                                          int N, int K, int m0, int n0,
                                          char* smem) {
    int tid = threadIdx.x;
    int lane = tid & 31;
    int wid = tid >> 5;
    int wr = wid >> 1, wc = wid & 1;

    uint32_t sbase = smem_u32(smem);

    auto load_stage = [&](int s, int k0) {
        uint32_t abase = sbase + A_SM_OFF + s * A_STG;
        uint32_t bbase = sbase + B_SM_OFF + s * B_STG;
        // A: 128 rows x 32 halves = 512 x 16B; 256 threads x 2
#pragma unroll
        for (int it = 0; it < 2; it++) {
            int idx = tid + it * 256;
            int r = idx >> 2, c = idx & 3;
            cp16(abase + (uint32_t)(r * ASTRIDE + c * 8) * 2,
                 &A[(size_t)(m0 + r) * K + k0 + c * 8]);
        }
        // B: 32 rows x 128 halves = 512 x 16B
#pragma unroll
        for (int it = 0; it < 2; it++) {
            int idx = tid + it * 256;
            int r = idx >> 4, c = idx & 15;
            cp16(bbase + (uint32_t)(r * BSTRIDE + c * 8) * 2,
                 &W[(size_t)(k0 + r) * N + n0 + c * 8]);
        }
        cp_commit();
    };

    float acc[2][8][4];
#pragma unroll
    for (int mi = 0; mi < 2; mi++)
#pragma unroll
        for (int n8 = 0; n8 < 8; n8++)
#pragma unroll
            for (int r = 0; r < 4; r++) acc[mi][n8][r] = 0.f;

    int nch = K / 32;
    load_stage(0, 0);
    load_stage(1, 32);

    for (int i = 0; i < nch; i++) {
        int s = i % 3;
        cp_wait<1>();
        __syncthreads();

        uint32_t a_base = sbase + A_SM_OFF + s * A_STG;
        uint32_t b_base = sbase + B_SM_OFF + s * B_STG;
#pragma unroll
        for (int kk = 0; kk < 2; kk++) {
            uint32_t af[2][4];
#pragma unroll
            for (int mi = 0; mi < 2; mi++) {
                int row = wr * 32 + mi * 16 + (lane & 15);
                int col = kk * 16 + (lane >> 4) * 8;
                ldsm_x4(af[mi][0], af[mi][1], af[mi][2], af[mi][3],
                        a_base + (uint32_t)(row * ASTRIDE + col) * 2);
            }
            uint32_t bf[4][4];
#pragma unroll
            for (int ni = 0; ni < 4; ni++) {
                int krow = kk * 16 + (lane & 15);
                int col = wc * 64 + ni * 16 + (lane >> 4) * 8;
                ldsm_x4_t(bf[ni][0], bf[ni][1], bf[ni][2], bf[ni][3],
                          b_base + (uint32_t)(krow * BSTRIDE + col) * 2);
            }
#pragma unroll
            for (int mi = 0; mi < 2; mi++)
#pragma unroll
                for (int ni = 0; ni < 4; ni++) {
                    mma_f16(acc[mi][ni * 2],     af[mi], &bf[ni][0]);
                    mma_f16(acc[mi][ni * 2 + 1], af[mi], &bf[ni][2]);
                }
        }
        __syncthreads();
        // FIX (round 8): always commit a group. Without the empty commit,
        // the final iteration's wait_group<1> is vacuous (only 1 pending
        // group) and compute races the last chunk's cp.async.
        if (i + 2 < nch) load_stage((i + 2) % 3, (i + 2) * 32);
        else             cp_commit();
    }

    // epilogue
#pragma unroll
    for (int mi = 0; mi < 2; mi++) {
        int row0 = m0 + wr * 32 + mi * 16 + (lane >> 2);
#pragma unroll
        for (int n8 = 0; n8 < 8; n8++) {
            int col = n0 + wc * 64 + n8 * 8 + (lane & 3) * 2;
            float2 bv = *(const float2*)&bias[col];
#pragma unroll
            for (int half = 0; half < 2; half++) {
                int row = row0 + half * 8;
                float vx = acc[mi][n8][half * 2 + 0] + bv.x;
                float vy = acc[mi][n8][half * 2 + 1] + bv.y;
                if (EPI == 1) { vx = gelu_exact(vx); vy = gelu_exact(vy); }
                if (EPI == 2) {
                    float2 rv = *(const float2*)&R[(size_t)row * N + col];
                    vx += rv.x; vy += rv.y;
                }
                if (sizeof(OutT) == 2) {
                    *(uint32_t*)&C[(size_t)row * N + col] = pack_h2(vx, vy);
                } else {
                    *(float2*)&C[(size_t)row * N + col] = make_float2(vx, vy);
                }
            }
        }
    }
}

template<int EPI, typename OutT>
__global__ __launch_bounds__(256, 2) void gemm_h(const __half* __restrict__ A,
                                                 const __half* __restrict__ W,
                                                 const float* __restrict__ bias,
                                                 const float* __restrict__ R,
                                                 OutT* __restrict__ C,
                                                 int N, int K) {
    extern __shared__ char smem[];
    gemm_body<EPI, OutT>(A, W, bias, R, C, N, K,
                         blockIdx.y * 128, blockIdx.x * 128, smem);
}

// fused QKV: grid.z selects weight/bias/output
__global__ __launch_bounds__(256, 2) void qkv_h(const __half* __restrict__ A,
                                                const __half* __restrict__ W0,
                                                const __half* __restrict__ W1,
                                                const __half* __restrict__ W2,
                                                const float* __restrict__ b0,
                                                const float* __restrict__ b1,
                                                const float* __restrict__ b2,
                                                __half* __restrict__ o0,
                                                __half* __restrict__ o1,
                                                __half* __restrict__ o2) {
    extern __shared__ char smem[];
    const __half* W = (blockIdx.z == 0) ? W0 : (blockIdx.z == 1) ? W1 : W2;
    const float* bias = (blockIdx.z == 0) ? b0 : (blockIdx.z == 1) ? b1 : b2;
    __half* O = (blockIdx.z == 0) ? o0 : (blockIdx.z == 1) ? o1 : o2;
    gemm_body<0, __half>(A, W, bias, nullptr, O, DIM, DIM,
                         blockIdx.y * 128, blockIdx.x * 128, smem);
}

// ------------------------ fp32 -> fp16 conversion --------------------------
__global__ __launch_bounds__(256) void f2h_kernel(const float* __restrict__ src,
                                                  __half* __restrict__ dst, int n4) {
    int i = blockIdx.x * 256 + threadIdx.x;
    if (i < n4) {
        float4 v = *(const float4*)&src[i * 4];
        uint2 u = {pack_h2(v.x, v.y), pack_h2(v.z, v.w)};
        *(uint2*)&dst[i * 4] = u;
    }
}

// ------------------------------ LayerNorm ----------------------------------
__global__ __launch_bounds__(256) void ln_kernel(const float* __restrict__ x,
                                                 const float* __restrict__ g,
                                                 const float* __restrict__ b,
                                                 __half* __restrict__ out) {
    int row = blockIdx.x;
    int tid = threadIdx.x;
    const float* xr = x + (size_t)row * DIM;
    __shared__ float buf[DIM];
    __shared__ float red[256];

    float s = 0.f;
    for (int i = tid; i < DIM; i += 256) { float v = xr[i]; buf[i] = v; s += v; }
    red[tid] = s; __syncthreads();
    for (int off = 128; off > 0; off >>= 1) {
        if (tid < off) red[tid] += red[tid + off];
        __syncthreads();
    }
    float mean = red[0] * (1.0f / DIM);
    __syncthreads();

    float vs = 0.f;
    for (int i = tid; i < DIM; i += 256) { float d = buf[i] - mean; vs += d * d; }
    red[tid] = vs; __syncthreads();
    for (int off = 128; off > 0; off >>= 1) {
        if (tid < off) red[tid] += red[tid + off];
        __syncthreads();
    }
    float rstd = rsqrtf(red[0] * (1.0f / DIM) + LN_EPS);

    __half* orow = out + (size_t)row * DIM;
    for (int i = tid; i < DIM; i += 256)
        orow[i] = __float2half((buf[i] - mean) * rstd * g[i] + b[i]);
}

// --------------------- flash attention on tensor cores ---------------------
#define FPAD 72

__global__ __launch_bounds__(128) void flash_mma(const __half* __restrict__ q,
                                                 const __half* __restrict__ k,
                                                 const __half* __restrict__ v,
                                                 __half* __restrict__ ctx) {
    int bh = blockIdx.z;
    int b = bh / HEADS, h = bh % HEADS;
    int qt = blockIdx.y;
    const __half* qb = q + (size_t)b * SEQ * DIM + h * HDIM;
    const __half* kb = k + (size_t)b * SEQ * DIM + h * HDIM;
    const __half* vb = v + (size_t)b * SEQ * DIM + h * HDIM;
    __half* ob = ctx + (size_t)b * SEQ * DIM + h * HDIM;

    __shared__ __half Qs[64][FPAD];
    __shared__ __half Ks[64][FPAD];
    __shared__ __half Vs[64][FPAD];

    int tid = threadIdx.x;
    int lane = tid & 31;
    int w = tid >> 5;

#pragma unroll
    for (int it = 0; it < 4; it++) {
        int idx = tid + it * 128;
        int r = idx >> 3, c8 = idx & 7;
        *(uint4*)&Qs[r][c8 * 8] = *(const uint4*)&qb[(size_t)(qt * 64 + r) * DIM + c8 * 8];
    }
    __syncthreads();

    uint32_t qf[4][4];
#pragma unroll
    for (int kk = 0; kk < 4; kk++) {
        int row = w * 16 + (lane & 15);
        int col = kk * 16 + (lane >> 4) * 8;
        ldsm_x4(qf[kk][0], qf[kk][1], qf[kk][2], qf[kk][3],
                smem_u32(&Qs[row][col]));
    }

    float m0 = -1e30f, m1 = -1e30f, l0 = 0.f, l1 = 0.f;
    float o[8][4];
#pragma unroll
    for (int j = 0; j < 8; j++)
#pragma unroll
        for (int r = 0; r < 4; r++) o[j][r] = 0.f;

    for (int t = 0; t < SEQ / 64; t++) {
#pragma unroll
        for (int it = 0; it < 4; it++) {
            int idx = tid + it * 128;
            int r = idx >> 3, c8 = idx & 7;
            *(uint4*)&Ks[r][c8 * 8] = *(const uint4*)&kb[(size_t)(t * 64 + r) * DIM + c8 * 8];
            *(uint4*)&Vs[r][c8 * 8] = *(const uint4*)&vb[(size_t)(t * 64 + r) * DIM + c8 * 8];
        }
        __syncthreads();

        float s[8][4];
#pragma unroll
        for (int j = 0; j < 8; j++)
#pragma unroll
            for (int r = 0; r < 4; r++) s[j][r] = 0.f;
#pragma unroll
        for (int kk = 0; kk < 4; kk++) {
#pragma unroll
            for (int nt = 0; nt < 4; nt++) {
                int krow = nt * 16 + (lane & 7) + ((lane >> 4) << 3);
                int kcol = kk * 16 + ((lane >> 3) & 1) * 8;
                uint32_t kf[4];
                ldsm_x4(kf[0], kf[1], kf[2], kf[3], smem_u32(&Ks[krow][kcol]));
                mma_f16(s[nt * 2],     qf[kk], &kf[0]);
                mma_f16(s[nt * 2 + 1], qf[kk], &kf[2]);
            }
        }

        float tm0 = -1e30f, tm1 = -1e30f;
#pragma unroll
        for (int j = 0; j < 8; j++) {
#pragma unroll
            for (int r = 0; r < 4; r++) s[j][r] *= 0.125f;
            tm0 = fmaxf(tm0, fmaxf(s[j][0], s[j][1]));
            tm1 = fmaxf(tm1, fmaxf(s[j][2], s[j][3]));
        }
#pragma unroll
        for (int mask = 1; mask <= 2; mask <<= 1) {
            tm0 = fmaxf(tm0, __shfl_xor_sync(0xffffffffu, tm0, mask));
            tm1 = fmaxf(tm1, __shfl_xor_sync(0xffffffffu, tm1, mask));
        }
        float mn0 = fmaxf(m0, tm0), mn1 = fmaxf(m1, tm1);
        float sc0 = __expf(m0 - mn0), sc1 = __expf(m1 - mn1);
        m0 = mn0; m1 = mn1;

        uint32_t ph0[8], ph1[8];
        float rs0 = 0.f, rs1 = 0.f;
#pragma unroll
        for (int j = 0; j < 8; j++) {
            float p0 = __expf(s[j][0] - mn0), p1 = __expf(s[j][1] - mn0);
            float p2 = __expf(s[j][2] - mn1), p3 = __expf(s[j][3] - mn1);
            rs0 += p0 + p1; rs1 += p2 + p3;
            ph0[j] = pack_h2(p0, p1);
            ph1[j] = pack_h2(p2, p3);
        }
#pragma unroll
        for (int mask = 1; mask <= 2; mask <<= 1) {
            rs0 += __shfl_xor_sync(0xffffffffu, rs0, mask);
            rs1 += __shfl_xor_sync(0xffffffffu, rs1, mask);
        }
        l0 = l0 * sc0 + rs0;
        l1 = l1 * sc1 + rs1;
#pragma unroll
        for (int j = 0; j < 8; j++) {
            o[j][0] *= sc0; o[j][1] *= sc0;
            o[j][2] *= sc1; o[j][3] *= sc1;
        }

#pragma unroll
        for (int kk = 0; kk < 4; kk++) {
            uint32_t a[4] = {ph0[2 * kk], ph1[2 * kk], ph0[2 * kk + 1], ph1[2 * kk + 1]};
#pragma unroll
            for (int nt = 0; nt < 4; nt++) {
                int vrow = kk * 16 + (lane & 15);
                int vcol = nt * 16 + (lane >> 4) * 8;
                uint32_t vf[4];
                ldsm_x4_t(vf[0], vf[1], vf[2], vf[3], smem_u32(&Vs[vrow][vcol]));
                mma_f16(o[nt * 2],     a, &vf[0]);
                mma_f16(o[nt * 2 + 1], a, &vf[2]);
            }
        }
        __syncthreads();
    }

    float inv0 = 1.0f / l0, inv1 = 1.0f / l1;
    int row0 = qt * 64 + w * 16 + (lane >> 2);
    int row1 = row0 + 8;
#pragma unroll
    for (int j = 0; j < 8; j++) {
        int col = (j >> 1) * 16 + (j & 1) * 8 + (lane & 3) * 2;
        *(uint32_t*)&ob[(size_t)row0 * DIM + col] = pack_h2(o[j][0] * inv0, o[j][1] * inv0);
        *(uint32_t*)&ob[(size_t)row1 * DIM + col] = pack_h2(o[j][2] * inv1, o[j][3] * inv1);
    }
}

// ------------------------------ launcher -----------------------------------
extern "C" void kernel_launch(void* const* d_in, const int* in_sizes, int n_in,
                              void* d_out, int out_size) {
    (void)in_sizes; (void)n_in; (void)out_size;
    const float* x     = (const float*)d_in[0];
    const float* ln1_g = (const float*)d_in[1];
    const float* ln1_b = (const float*)d_in[2];
    const float* Wq    = (const float*)d_in[3];
    const float* bq    = (const float*)d_in[4];
    const float* Wk    = (const float*)d_in[5];
    const float* bk    = (const float*)d_in[6];
    const float* Wv    = (const float*)d_in[7];
    const float* bv    = (const float*)d_in[8];
    const float* Wo    = (const float*)d_in[9];
    const float* bo    = (const float*)d_in[10];
    const float* ln2_g = (const float*)d_in[11];
    const float* ln2_b = (const float*)d_in[12];
    const float* W1    = (const float*)d_in[13];
    const float* b1    = (const float*)d_in[14];
    const float* W2    = (const float*)d_in[15];
    const float* b2    = (const float*)d_in[16];
    float* out = (float*)d_out;

    __half *xnh, *qh, *kh, *vh, *ctxh, *xn2h, *h1h;
    __half *Wqh, *Wkh, *Wvh, *Woh, *W1h, *W2h;
    float *x1;
    cudaGetSymbolAddress((void**)&xnh,  g_xnh);
    cudaGetSymbolAddress((void**)&qh,   g_qh);
    cudaGetSymbolAddress((void**)&kh,   g_kh);
    cudaGetSymbolAddress((void**)&vh,   g_vh);
    cudaGetSymbolAddress((void**)&ctxh, g_ctxh);
    cudaGetSymbolAddress((void**)&x1,   g_x1);
    cudaGetSymbolAddress((void**)&xn2h, g_xn2h);
    cudaGetSymbolAddress((void**)&h1h,  g_h1h);
    cudaGetSymbolAddress((void**)&Wqh,  g_Wqh);
    cudaGetSymbolAddress((void**)&Wkh,  g_Wkh);
    cudaGetSymbolAddress((void**)&Wvh,  g_Wvh);
    cudaGetSymbolAddress((void**)&Woh,  g_Woh);
    cudaGetSymbolAddress((void**)&W1h,  g_W1h);
    cudaGetSymbolAddress((void**)&W2h,  g_W2h);

    cudaFuncSetAttribute(gemm_h<0, __half>, cudaFuncAttributeMaxDynamicSharedMemorySize, GEMM_SMEM);
    cudaFuncSetAttribute(gemm_h<1, __half>, cudaFuncAttributeMaxDynamicSharedMemorySize, GEMM_SMEM);
    cudaFuncSetAttribute(gemm_h<2, float>,  cudaFuncAttributeMaxDynamicSharedMemorySize, GEMM_SMEM);
    cudaFuncSetAttribute(qkv_h, cudaFuncAttributeMaxDynamicSharedMemorySize, GEMM_SMEM);

    // 0. convert weights to fp16
    f2h_kernel<<<(DIM * DIM / 4 + 255) / 256, 256>>>(Wq, Wqh, DIM * DIM / 4);
    f2h_kernel<<<(DIM * DIM / 4 + 255) / 256, 256>>>(Wk, Wkh, DIM * DIM / 4);
    f2h_kernel<<<(DIM * DIM / 4 + 255) / 256, 256>>>(Wv, Wvh, DIM * DIM / 4);
    f2h_kernel<<<(DIM * DIM / 4 + 255) / 256, 256>>>(Wo, Woh, DIM * DIM / 4);
    f2h_kernel<<<(DIM * DFF / 4 + 255) / 256, 256>>>(W1, W1h, DIM * DFF / 4);
    f2h_kernel<<<(DFF * DIM / 4 + 255) / 256, 256>>>(W2, W2h, DFF * DIM / 4);

    // 1. LN1 -> fp16
    ln_kernel<<<TOKENS, 256>>>(x, ln1_g, ln1_b, xnh);

    // 2. fused QKV (fp16 in/out)
    qkv_h<<<dim3(DIM / 128, TOKENS / 128, 3), 256, GEMM_SMEM>>>(
        xnh, Wqh, Wkh, Wvh, bq, bk, bv, qh, kh, vh);

    // 3. flash attention -> fp16 ctx
    flash_mma<<<dim3(1, SEQ / 64, BATCH * HEADS), 128>>>(qh, kh, vh, ctxh);

    // 4. Wo + residual(x) -> fp32 x1
    gemm_h<2, float><<<dim3(DIM / 128, TOKENS / 128), 256, GEMM_SMEM>>>(
        ctxh, Woh, bo, x, x1, DIM, DIM);

    // 5. LN2 -> fp16
    ln_kernel<<<TOKENS, 256>>>(x1, ln2_g, ln2_b, xn2h);

    // 6. W1 + GELU -> fp16 h1
    gemm_h<1, __half><<<dim3(DFF / 128, TOKENS / 128), 256, GEMM_SMEM>>>(
        xn2h, W1h, b1, nullptr, h1h, DFF, DIM);

    // 7. W2 + residual(x1) -> fp32 out
    gemm_h<2, float><<<dim3(DIM / 128, TOKENS / 128), 256, GEMM_SMEM>>>(
        h1h, W2h, b2, x1, out, DIM, DFF);
}